// round 3
// baseline (speedup 1.0000x reference)
#include <cuda_runtime.h>
#include <cuda_bf16.h>
#include <math.h>
#include <stdint.h>

#define B_ 16
#define T_ 2000
#define U_ 400
#define D_ 512
#define C_ 4096
#define M_ (B_ * T_)   // 32000
#define NEGF (-1e30f)

// ---------------- device scratch ----------------
__device__ __align__(16) __nv_bfloat16 g_logits[(size_t)M_ * C_];  // 256 MB
__device__ float g_lse[M_];
__device__ float g_lp[(size_t)2 * B_ * T_ * U_];                   // 102 MB
__device__ float g_loss[2 * B_];
__device__ __align__(16) __nv_bfloat16 g_xb[(size_t)M_ * D_];
__device__ __align__(16) __nv_bfloat16 g_Wb[(size_t)D_ * C_];

__device__ __forceinline__ float laef(float a, float b) {
    float mx = fmaxf(a, b);
    float d  = fminf(a, b) - mx;
    return mx + __logf(1.0f + __expf(d));
}

// ---------------- 0) fp32 -> bf16 conversion ----------------
__device__ __forceinline__ void cvt8(const float* __restrict__ in,
                                     __nv_bfloat16* __restrict__ out, int i) {
    const float4* p = (const float4*)in + (size_t)i * 2;
    float4 v0 = p[0], v1 = p[1];
    __nv_bfloat162 b0 = __floats2bfloat162_rn(v0.x, v0.y);
    __nv_bfloat162 b1 = __floats2bfloat162_rn(v0.z, v0.w);
    __nv_bfloat162 b2 = __floats2bfloat162_rn(v1.x, v1.y);
    __nv_bfloat162 b3 = __floats2bfloat162_rn(v1.z, v1.w);
    uint4 o;
    o.x = *reinterpret_cast<unsigned*>(&b0);
    o.y = *reinterpret_cast<unsigned*>(&b1);
    o.z = *reinterpret_cast<unsigned*>(&b2);
    o.w = *reinterpret_cast<unsigned*>(&b3);
    *((uint4*)out + i) = o;
}

__global__ __launch_bounds__(256) void cvt_x_kernel(const float* __restrict__ in) {
    int i = blockIdx.x * 256 + threadIdx.x;
    if (i < (M_ * D_) / 8) cvt8(in, g_xb, i);
}
__global__ __launch_bounds__(256) void cvt_w_kernel(const float* __restrict__ in) {
    int i = blockIdx.x * 256 + threadIdx.x;
    if (i < (D_ * C_) / 8) cvt8(in, g_Wb, i);
}

// ---------------- 1) bf16 tensor-core GEMM ----------------
#define PADA 8
#define PADB 8
__global__ __launch_bounds__(256) void gemm_bf16_kernel(const float* __restrict__ bias)
{
    __shared__ __nv_bfloat16 As[2][128][16 + PADA];
    __shared__ __nv_bfloat16 Bs[2][16][128 + PADB];

    const int tid = threadIdx.x;
    const int wid = tid >> 5, lane = tid & 31;
    const int bm = blockIdx.y, bn = blockIdx.x;
    const int wm = wid & 1, wn = wid >> 1;   // warps: 2 (m) x 4 (n), each 64x32

    const int arow = tid >> 1, acol = (tid & 1) * 8;
    const int brow = tid >> 4, bcol = (tid & 15) * 8;
    const __nv_bfloat16* gA = g_xb + (size_t)(bm * 128 + arow) * D_ + acol;
    const __nv_bfloat16* gB = g_Wb + (size_t)brow * C_ + bn * 128 + bcol;

    const int aRow = wm * 64 + (lane & 7) + ((lane >> 3) & 1) * 8;
    const int aCol = ((lane >> 4) & 1) * 8;
    const int bRow = (lane & 7) + ((lane >> 3) & 1) * 8;
    const int bColBase = wn * 32 + ((lane >> 4) & 1) * 8;

    const uint32_t aBase = (uint32_t)__cvta_generic_to_shared(&As[0][0][0]);
    const uint32_t bBase = (uint32_t)__cvta_generic_to_shared(&Bs[0][0][0]);
    const uint32_t AbufSz = sizeof(As[0]);
    const uint32_t BbufSz = sizeof(Bs[0]);

    float acc[4][4][4];
#pragma unroll
    for (int mt = 0; mt < 4; mt++)
#pragma unroll
        for (int nt = 0; nt < 4; nt++)
#pragma unroll
            for (int j = 0; j < 4; j++) acc[mt][nt][j] = 0.0f;

    *(uint4*)&As[0][arow][acol] = *(const uint4*)gA;
    *(uint4*)&Bs[0][brow][bcol] = *(const uint4*)gB;
    __syncthreads();

    const int NKT = D_ / 16;   // 32
    for (int kt = 0; kt < NKT; kt++) {
        const int buf = kt & 1;
        uint4 la, lb;
        if (kt + 1 < NKT) {
            la = *(const uint4*)(gA + (kt + 1) * 16);
            lb = *(const uint4*)(gB + (size_t)(kt + 1) * 16 * C_);
        }

        uint32_t a[4][4], b[2][4];
#pragma unroll
        for (int mt = 0; mt < 4; mt++) {
            uint32_t addr = aBase + buf * AbufSz +
                            ((aRow + mt * 16) * (16 + PADA) + aCol) * 2;
            asm volatile("ldmatrix.sync.aligned.m8n8.x4.shared.b16 {%0,%1,%2,%3}, [%4];"
                : "=r"(a[mt][0]), "=r"(a[mt][1]), "=r"(a[mt][2]), "=r"(a[mt][3])
                : "r"(addr));
        }
#pragma unroll
        for (int pr = 0; pr < 2; pr++) {
            uint32_t addr = bBase + buf * BbufSz +
                            (bRow * (128 + PADB) + bColBase + pr * 16) * 2;
            asm volatile("ldmatrix.sync.aligned.m8n8.x4.trans.shared.b16 {%0,%1,%2,%3}, [%4];"
                : "=r"(b[pr][0]), "=r"(b[pr][1]), "=r"(b[pr][2]), "=r"(b[pr][3])
                : "r"(addr));
        }

#pragma unroll
        for (int mt = 0; mt < 4; mt++)
#pragma unroll
            for (int nt = 0; nt < 4; nt++) {
                uint32_t b0 = b[nt >> 1][(nt & 1) * 2 + 0];
                uint32_t b1 = b[nt >> 1][(nt & 1) * 2 + 1];
                asm volatile(
                    "mma.sync.aligned.m16n8k16.row.col.f32.bf16.bf16.f32 "
                    "{%0,%1,%2,%3}, {%4,%5,%6,%7}, {%8,%9}, {%0,%1,%2,%3};"
                    : "+f"(acc[mt][nt][0]), "+f"(acc[mt][nt][1]),
                      "+f"(acc[mt][nt][2]), "+f"(acc[mt][nt][3])
                    : "r"(a[mt][0]), "r"(a[mt][1]), "r"(a[mt][2]), "r"(a[mt][3]),
                      "r"(b0), "r"(b1));
            }

        if (kt + 1 < NKT) {
            int nb = buf ^ 1;
            *(uint4*)&As[nb][arow][acol] = la;
            *(uint4*)&Bs[nb][brow][bcol] = lb;
        }
        __syncthreads();
    }

    // epilogue: add bias, pack bf16x2, store
    const int tig = lane & 3, grp = lane >> 2;
#pragma unroll
    for (int mt = 0; mt < 4; mt++) {
        int row0 = bm * 128 + wm * 64 + mt * 16 + grp;
#pragma unroll
        for (int nt = 0; nt < 4; nt++) {
            int col = bn * 128 + wn * 32 + nt * 8 + 2 * tig;
            float b0v = bias[col], b1v = bias[col + 1];
            __nv_bfloat162 p0 = __floats2bfloat162_rn(acc[mt][nt][0] + b0v,
                                                      acc[mt][nt][1] + b1v);
            __nv_bfloat162 p1 = __floats2bfloat162_rn(acc[mt][nt][2] + b0v,
                                                      acc[mt][nt][3] + b1v);
            *(__nv_bfloat162*)&g_logits[(size_t)row0 * C_ + col] = p0;
            *(__nv_bfloat162*)&g_logits[(size_t)(row0 + 8) * C_ + col] = p1;
        }
    }
}

// ---------------- 2) per-row logsumexp (bf16 input) ----------------
__global__ __launch_bounds__(256) void lse_kernel()
{
    int r = blockIdx.x;
    const uint4* row = (const uint4*)(g_logits + (size_t)r * C_);  // 512 uint4/row
    int tid = threadIdx.x;

    uint4 v0 = row[tid], v1 = row[tid + 256];
    uint32_t w[8] = {v0.x, v0.y, v0.z, v0.w, v1.x, v1.y, v1.z, v1.w};
    float f[16];
#pragma unroll
    for (int i = 0; i < 8; i++) {
        float2 p = __bfloat1622float2(*reinterpret_cast<__nv_bfloat162*>(&w[i]));
        f[2 * i] = p.x; f[2 * i + 1] = p.y;
    }

    float mx = -1e30f;
#pragma unroll
    for (int i = 0; i < 16; i++) mx = fmaxf(mx, f[i]);

    __shared__ float red[256];
    red[tid] = mx;
    __syncthreads();
    for (int s = 128; s > 0; s >>= 1) {
        if (tid < s) red[tid] = fmaxf(red[tid], red[tid + s]);
        __syncthreads();
    }
    mx = red[0];
    __syncthreads();

    float sum = 0.0f;
#pragma unroll
    for (int i = 0; i < 16; i++) sum += __expf(f[i] - mx);
    red[tid] = sum;
    __syncthreads();
    for (int s = 128; s > 0; s >>= 1) {
        if (tid < s) red[tid] += red[tid + s];
        __syncthreads();
    }
    if (tid == 0) g_lse[r] = mx + __logf(red[0]);
}

// ---------------- 3) gather lp ----------------
#define GT 8
__global__ __launch_bounds__(128) void gather_kernel(
    const int* __restrict__ tgt1, const int* __restrict__ tgt2,
    const int* __restrict__ act_lens,
    const int* __restrict__ tl1, const int* __restrict__ tl2)
{
    int chain = blockIdx.y;
    int s = chain >> 4, b = chain & 15;
    const int* tgt = (s ? tgt2 : tgt1) + b * U_;
    int tlen = (s ? tl2 : tl1)[b];
    int alen = act_lens[b];

    int t0 = blockIdx.x * GT;
    if (t0 >= alen) return;
    int te = min(t0 + GT, alen);

    int tid = threadIdx.x;
    int c[4];
    int nu = 0;
    for (int u = tid; u < tlen; u += 128) c[nu++] = tgt[u];

    float* lpc = g_lp + (size_t)chain * T_ * U_;
    for (int t = t0; t < te; t++) {
        const __nv_bfloat16* lrow = g_logits + (size_t)(b * T_ + t) * C_;
        float lse = g_lse[b * T_ + t];
        float* lprow = lpc + (size_t)t * U_;
        int u = tid;
        for (int i = 0; i < nu; i++, u += 128)
            lprow[u] = __bfloat162float(__ldg(lrow + c[i])) - lse;
    }
}

// ---------------- 4) alpha recursion: 4 warps per chain ----------------
__device__ __forceinline__ void alpha_step(float4& a, const float4& c,
                                           float up, bool act)
{
    if (act) {
        float n0 = laef(a.x, up)  + c.x;
        float n1 = laef(a.y, a.x) + c.y;
        float n2 = laef(a.z, a.y) + c.z;
        float n3 = laef(a.w, a.z) + c.w;
        a.x = n0; a.y = n1; a.z = n2; a.w = n3;
    }
}

__global__ __launch_bounds__(128) void alpha_kernel(
    const int* __restrict__ act_lens,
    const int* __restrict__ tl1, const int* __restrict__ tl2)
{
    int chain = blockIdx.x;
    int s = chain >> 4, b = chain & 15;
    int tlen = (s ? tl2 : tl1)[b];
    int alen = act_lens[b];          // >= 1000
    int tid = threadIdx.x, warp = tid >> 5, lane = tid & 31;
    const float* lp = g_lp + (size_t)chain * T_ * U_;
    int u0 = tid * 4;
    bool ldok = u0 < U_;             // float4 load in-range (u0 <= 396)
    bool act  = u0 < tlen;           // contributes to result

    __shared__ float4 sbuf[2][128];
    __shared__ float bnd[2][4];

    const float4 z = make_float4(NEGF, NEGF, NEGF, NEGF);

    // init alpha from row 0
    float4 f0 = ldok ? *(const float4*)(lp + u0) : z;
    float4 a;
    a.x = f0.x + ((u0 == 0) ? 0.0f : NEGF);
    a.y = f0.y + NEGF;
    a.z = f0.z + NEGF;
    a.w = f0.w + NEGF;

    // prologue: rows 1,2 -> smem; rows 3,4 -> prefetch regs (alen >= 1000)
    sbuf[1][tid] = ldok ? *(const float4*)(lp + (size_t)1 * U_ + u0) : z;
    sbuf[0][tid] = ldok ? *(const float4*)(lp + (size_t)2 * U_ + u0) : z;
    float4 pfA = ldok ? *(const float4*)(lp + (size_t)3 * U_ + u0) : z;
    float4 pfB = ldok ? *(const float4*)(lp + (size_t)4 * U_ + u0) : z;

    int t = 1;
    for (; t + 1 < alen; t += 2) {
        // ---- phase A: row t (odd) in sbuf[1] ----
        if (lane == 31) bnd[1][warp] = a.w;
        __syncthreads();
        float4 c = sbuf[1][tid];
        float up = __shfl_up_sync(0xffffffffu, a.w, 1);
        if (lane == 0) up = warp ? bnd[1][warp - 1] : NEGF;
        alpha_step(a, c, up, act);
        sbuf[1][tid] = pfA;
        pfA = (ldok && t + 4 < alen) ? *(const float4*)(lp + (size_t)(t + 4) * U_ + u0) : z;

        // ---- phase B: row t+1 (even) in sbuf[0] ----
        if (lane == 31) bnd[0][warp] = a.w;
        __syncthreads();
        c = sbuf[0][tid];
        up = __shfl_up_sync(0xffffffffu, a.w, 1);
        if (lane == 0) up = warp ? bnd[0][warp - 1] : NEGF;
        alpha_step(a, c, up, act);
        sbuf[0][tid] = pfB;
        pfB = (ldok && t + 5 < alen) ? *(const float4*)(lp + (size_t)(t + 5) * U_ + u0) : z;
    }
    if (t < alen) {   // one remaining odd row in sbuf[1]
        if (lane == 31) bnd[1][warp] = a.w;
        __syncthreads();
        float4 c = sbuf[1][tid];
        float up = __shfl_up_sync(0xffffffffu, a.w, 1);
        if (lane == 0) up = warp ? bnd[1][warp - 1] : NEGF;
        alpha_step(a, c, up, act);
    }

    int ustar = tlen - 1;
    if (tid == (ustar >> 2)) {
        int j = ustar & 3;
        float v = (j == 0) ? a.x : (j == 1) ? a.y : (j == 2) ? a.z : a.w;
        g_loss[chain] = -v;
    }
}

// ---------------- 5) final reduction ----------------
__global__ void loss_kernel(float* out)
{
    if (threadIdx.x == 0) {
        float l1 = 0.0f, l2 = 0.0f;
        for (int i = 0; i < 16; i++) { l1 += g_loss[i]; l2 += g_loss[16 + i]; }
        l1 *= (1.0f / 16.0f);
        l2 *= (1.0f / 16.0f);
        out[0] = l1 - 0.5f * l2;
        out[1] = l1;
        out[2] = l2;
    }
}

// ---------------- launch ----------------
extern "C" void kernel_launch(void* const* d_in, const int* in_sizes, int n_in,
                              void* d_out, int out_size)
{
    const float* x    = (const float*)d_in[0];
    const float* W    = (const float*)d_in[1];
    const float* bias = (const float*)d_in[2];
    const int* tgt1   = (const int*)d_in[3];
    const int* tgt2   = (const int*)d_in[4];
    const int* alen   = (const int*)d_in[5];
    const int* tl1    = (const int*)d_in[6];
    const int* tl2    = (const int*)d_in[7];
    float* out = (float*)d_out;

    cvt_x_kernel<<<(M_ * D_ / 8 + 255) / 256, 256>>>(x);
    cvt_w_kernel<<<(D_ * C_ / 8 + 255) / 256, 256>>>(W);

    dim3 ggrid(C_ / 128, M_ / 128);          // (32, 250)
    gemm_bf16_kernel<<<ggrid, 256>>>(bias);

    lse_kernel<<<M_, 256>>>();

    dim3 grid_g((T_ + GT - 1) / GT, 2 * B_); // (250, 32)
    gather_kernel<<<grid_g, 128>>>(tgt1, tgt2, alen, tl1, tl2);

    alpha_kernel<<<2 * B_, 128>>>(alen, tl1, tl2);

    loss_kernel<<<1, 32>>>(out);
}

// round 4
// speedup vs baseline: 1.0511x; 1.0511x over previous
#include <cuda_runtime.h>
#include <cuda_bf16.h>
#include <math.h>
#include <stdint.h>

#define B_ 16
#define T_ 2000
#define U_ 400
#define D_ 512
#define C_ 4096
#define M_ (B_ * T_)   // 32000
#define NEGF (-1e30f)

// ---------------- device scratch ----------------
__device__ __align__(16) __nv_bfloat16 g_logits[(size_t)M_ * C_];  // 256 MB
__device__ float g_lse[M_];
__device__ float g_lp[(size_t)2 * B_ * T_ * U_];                   // 102 MB
__device__ float g_loss[2 * B_];
__device__ __align__(16) __nv_bfloat16 g_xb[(size_t)M_ * D_];
__device__ __align__(16) __nv_bfloat16 g_Wb[(size_t)D_ * C_];

__device__ __forceinline__ float laef(float a, float b) {
    float mx = fmaxf(a, b);
    float d  = fminf(a, b) - mx;
    return mx + __logf(1.0f + __expf(d));
}

// ---------------- 0) fp32 -> bf16 conversion ----------------
__device__ __forceinline__ void cvt8(const float* __restrict__ in,
                                     __nv_bfloat16* __restrict__ out, int i) {
    const float4* p = (const float4*)in + (size_t)i * 2;
    float4 v0 = p[0], v1 = p[1];
    __nv_bfloat162 b0 = __floats2bfloat162_rn(v0.x, v0.y);
    __nv_bfloat162 b1 = __floats2bfloat162_rn(v0.z, v0.w);
    __nv_bfloat162 b2 = __floats2bfloat162_rn(v1.x, v1.y);
    __nv_bfloat162 b3 = __floats2bfloat162_rn(v1.z, v1.w);
    uint4 o;
    o.x = *reinterpret_cast<unsigned*>(&b0);
    o.y = *reinterpret_cast<unsigned*>(&b1);
    o.z = *reinterpret_cast<unsigned*>(&b2);
    o.w = *reinterpret_cast<unsigned*>(&b3);
    *((uint4*)out + i) = o;
}

__global__ __launch_bounds__(256) void cvt_x_kernel(const float* __restrict__ in) {
    int i = blockIdx.x * 256 + threadIdx.x;
    if (i < (M_ * D_) / 8) cvt8(in, g_xb, i);
}
__global__ __launch_bounds__(256) void cvt_w_kernel(const float* __restrict__ in) {
    int i = blockIdx.x * 256 + threadIdx.x;
    if (i < (D_ * C_) / 8) cvt8(in, g_Wb, i);
}

// slot-shifter so ncu capture (lands on 4th launch) profiles the GEMM
__global__ void noop_kernel() {}

// ---------------- 1) bf16 tensor-core GEMM, cp.async 3-stage ----------------
#define BK 32
#define STG 3
#define PA 8                      // A row pitch = BK+PA = 40 elems (80 B)
#define PB 8                      // B row pitch = 128+PB = 136 elems (272 B)

__device__ __forceinline__ void cpa16(uint32_t dst, const void* src) {
    asm volatile("cp.async.cg.shared.global [%0], [%1], 16;\n"
                 :: "r"(dst), "l"(src));
}
__device__ __forceinline__ void cpa_commit() {
    asm volatile("cp.async.commit_group;\n" ::: "memory");
}
template <int N>
__device__ __forceinline__ void cpa_wait() {
    asm volatile("cp.async.wait_group %0;\n" :: "n"(N) : "memory");
}

__global__ __launch_bounds__(256) void gemm_bf16_kernel(const float* __restrict__ bias)
{
    __shared__ __nv_bfloat16 As[STG][128][BK + PA];   // 3*128*40*2 = 30720 B
    __shared__ __nv_bfloat16 Bs[STG][BK][128 + PB];   // 3*32*136*2 = 26112 B

    const int tid = threadIdx.x;
    const int wid = tid >> 5, lane = tid & 31;
    const int bm = blockIdx.y, bn = blockIdx.x;
    const int wm = wid & 1, wn = wid >> 1;   // 2 (m) x 4 (n) warps, each 64x32

    // cp.async staging: A tile 128x32 = 512 16B-chunks; B tile 32x128 = 512 chunks
    const int aRowLd0 = (tid * 2) >> 2,      aChkLd0 = (tid * 2) & 3;       // chunks c=2*tid, 2*tid+1
    const int bRowLd0 = (tid * 2) >> 4,      bChkLd0 = (tid * 2) & 15;

    const __nv_bfloat16* gAr = g_xb + (size_t)(bm * 128) * D_;
    const __nv_bfloat16* gBr = g_Wb + (size_t)0 * C_ + bn * 128;

    const uint32_t aBase = (uint32_t)__cvta_generic_to_shared(&As[0][0][0]);
    const uint32_t bBase = (uint32_t)__cvta_generic_to_shared(&Bs[0][0][0]);
    const uint32_t AstgSz = sizeof(As[0]);
    const uint32_t BstgSz = sizeof(Bs[0]);

    // issue one stage's copies (A: 2 chunks, B: 2 chunks per thread)
    auto issue = [&](int s, int k0) {
#pragma unroll
        for (int l = 0; l < 2; l++) {
            int c = tid * 2 + l;
            int ar = c >> 2, ac = (c & 3) * 8;
            cpa16(aBase + s * AstgSz + (ar * (BK + PA) + ac) * 2,
                  gAr + (size_t)ar * D_ + k0 + ac);
        }
#pragma unroll
        for (int l = 0; l < 2; l++) {
            int c = tid * 2 + l;
            int br = c >> 4, bc = (c & 15) * 8;
            cpa16(bBase + s * BstgSz + (br * (128 + PB) + bc) * 2,
                  gBr + (size_t)(k0 + br) * C_ + bc);
        }
    };

    // ldmatrix lane addressing
    const int aRow = wm * 64 + (lane & 7) + ((lane >> 3) & 1) * 8;  // + mt*16
    const int aColHalf = ((lane >> 4) & 1) * 8;                     // + ks*16
    const int bRowHalf = (lane & 7) + ((lane >> 3) & 1) * 8;        // + ks*16
    const int bColBase = wn * 32 + ((lane >> 4) & 1) * 8;           // + pr*16

    float acc[4][4][4];
#pragma unroll
    for (int mt = 0; mt < 4; mt++)
#pragma unroll
        for (int nt = 0; nt < 4; nt++)
#pragma unroll
            for (int j = 0; j < 4; j++) acc[mt][nt][j] = 0.0f;

    // prologue: stages 0,1 in flight
    issue(0, 0);  cpa_commit();
    issue(1, BK); cpa_commit();

    const int NKT = D_ / BK;   // 16
#pragma unroll 1
    for (int kt = 0; kt < NKT; kt++) {
        cpa_wait<1>();          // stage kt landed
        __syncthreads();

        if (kt + 2 < NKT) issue((kt + 2) % STG, (kt + 2) * BK);
        cpa_commit();

        const int p = kt % STG;
#pragma unroll
        for (int ks = 0; ks < 2; ks++) {
            uint32_t a[4][4], b[2][4];
#pragma unroll
            for (int mt = 0; mt < 4; mt++) {
                uint32_t addr = aBase + p * AstgSz +
                    ((aRow + mt * 16) * (BK + PA) + ks * 16 + aColHalf) * 2;
                asm volatile("ldmatrix.sync.aligned.m8n8.x4.shared.b16 {%0,%1,%2,%3}, [%4];"
                    : "=r"(a[mt][0]), "=r"(a[mt][1]), "=r"(a[mt][2]), "=r"(a[mt][3])
                    : "r"(addr));
            }
#pragma unroll
            for (int pr = 0; pr < 2; pr++) {
                uint32_t addr = bBase + p * BstgSz +
                    ((ks * 16 + bRowHalf) * (128 + PB) + bColBase + pr * 16) * 2;
                asm volatile("ldmatrix.sync.aligned.m8n8.x4.trans.shared.b16 {%0,%1,%2,%3}, [%4];"
                    : "=r"(b[pr][0]), "=r"(b[pr][1]), "=r"(b[pr][2]), "=r"(b[pr][3])
                    : "r"(addr));
            }
#pragma unroll
            for (int mt = 0; mt < 4; mt++)
#pragma unroll
                for (int nt = 0; nt < 4; nt++) {
                    uint32_t b0 = b[nt >> 1][(nt & 1) * 2 + 0];
                    uint32_t b1 = b[nt >> 1][(nt & 1) * 2 + 1];
                    asm volatile(
                        "mma.sync.aligned.m16n8k16.row.col.f32.bf16.bf16.f32 "
                        "{%0,%1,%2,%3}, {%4,%5,%6,%7}, {%8,%9}, {%0,%1,%2,%3};"
                        : "+f"(acc[mt][nt][0]), "+f"(acc[mt][nt][1]),
                          "+f"(acc[mt][nt][2]), "+f"(acc[mt][nt][3])
                        : "r"(a[mt][0]), "r"(a[mt][1]), "r"(a[mt][2]), "r"(a[mt][3]),
                          "r"(b0), "r"(b1));
                }
        }
        __syncthreads();
    }

    // epilogue: add bias, pack bf16x2, store
    const int tig = lane & 3, grp = lane >> 2;
#pragma unroll
    for (int mt = 0; mt < 4; mt++) {
        int row0 = bm * 128 + wm * 64 + mt * 16 + grp;
#pragma unroll
        for (int nt = 0; nt < 4; nt++) {
            int col = bn * 128 + wn * 32 + nt * 8 + 2 * tig;
            float b0v = bias[col], b1v = bias[col + 1];
            __nv_bfloat162 p0 = __floats2bfloat162_rn(acc[mt][nt][0] + b0v,
                                                      acc[mt][nt][1] + b1v);
            __nv_bfloat162 p1 = __floats2bfloat162_rn(acc[mt][nt][2] + b0v,
                                                      acc[mt][nt][3] + b1v);
            *(__nv_bfloat162*)&g_logits[(size_t)row0 * C_ + col] = p0;
            *(__nv_bfloat162*)&g_logits[(size_t)(row0 + 8) * C_ + col] = p1;
        }
    }
}

// ---------------- 2) per-row logsumexp (bf16 input) ----------------
__global__ __launch_bounds__(256) void lse_kernel()
{
    int r = blockIdx.x;
    const uint4* row = (const uint4*)(g_logits + (size_t)r * C_);
    int tid = threadIdx.x;

    uint4 v0 = row[tid], v1 = row[tid + 256];
    uint32_t w[8] = {v0.x, v0.y, v0.z, v0.w, v1.x, v1.y, v1.z, v1.w};
    float f[16];
#pragma unroll
    for (int i = 0; i < 8; i++) {
        float2 p = __bfloat1622float2(*reinterpret_cast<__nv_bfloat162*>(&w[i]));
        f[2 * i] = p.x; f[2 * i + 1] = p.y;
    }

    float mx = -1e30f;
#pragma unroll
    for (int i = 0; i < 16; i++) mx = fmaxf(mx, f[i]);

    __shared__ float red[256];
    red[tid] = mx;
    __syncthreads();
    for (int s = 128; s > 0; s >>= 1) {
        if (tid < s) red[tid] = fmaxf(red[tid], red[tid + s]);
        __syncthreads();
    }
    mx = red[0];
    __syncthreads();

    float sum = 0.0f;
#pragma unroll
    for (int i = 0; i < 16; i++) sum += __expf(f[i] - mx);
    red[tid] = sum;
    __syncthreads();
    for (int s = 128; s > 0; s >>= 1) {
        if (tid < s) red[tid] += red[tid + s];
        __syncthreads();
    }
    if (tid == 0) g_lse[r] = mx + __logf(red[0]);
}

// ---------------- 3) gather lp ----------------
#define GT 8
__global__ __launch_bounds__(128) void gather_kernel(
    const int* __restrict__ tgt1, const int* __restrict__ tgt2,
    const int* __restrict__ act_lens,
    const int* __restrict__ tl1, const int* __restrict__ tl2)
{
    int chain = blockIdx.y;
    int s = chain >> 4, b = chain & 15;
    const int* tgt = (s ? tgt2 : tgt1) + b * U_;
    int tlen = (s ? tl2 : tl1)[b];
    int alen = act_lens[b];

    int t0 = blockIdx.x * GT;
    if (t0 >= alen) return;
    int te = min(t0 + GT, alen);

    int tid = threadIdx.x;
    int c[4];
    int nu = 0;
    for (int u = tid; u < tlen; u += 128) c[nu++] = tgt[u];

    float* lpc = g_lp + (size_t)chain * T_ * U_;
    for (int t = t0; t < te; t++) {
        const __nv_bfloat16* lrow = g_logits + (size_t)(b * T_ + t) * C_;
        float lse = g_lse[b * T_ + t];
        float* lprow = lpc + (size_t)t * U_;
        int u = tid;
        for (int i = 0; i < nu; i++, u += 128)
            lprow[u] = __bfloat162float(__ldg(lrow + c[i])) - lse;
    }
}

// ---------------- 4) alpha recursion: ONE WARP per chain ----------------
#define E_ 13   // 13*32 = 416 >= U_
__device__ __forceinline__ void stepf(float* a, const float* c, int lane)
{
    float up = __shfl_up_sync(0xffffffffu, a[E_ - 1], 1);
    if (lane == 0) up = NEGF;
    float prev = up;
#pragma unroll
    for (int i = 0; i < E_; i++) {
        float old = a[i];
        a[i] = laef(old, prev) + c[i];
        prev = old;
    }
}

__global__ __launch_bounds__(32) void alpha_kernel(
    const int* __restrict__ act_lens,
    const int* __restrict__ tl1, const int* __restrict__ tl2)
{
    int chain = blockIdx.x;
    int s = chain >> 4, b = chain & 15;
    int tlen = (s ? tl2 : tl1)[b];
    int alen = act_lens[b];          // >= 1000
    int lane = threadIdx.x;
    const float* lp = g_lp + (size_t)chain * T_ * U_;

    __shared__ float sb[2][416];
    float a[E_], pfA[E_], pfB[E_];
    int u0 = lane * E_;

#pragma unroll
    for (int i = 0; i < E_; i++) {
        int u = u0 + i;
        float v = (u < U_) ? lp[u] : NEGF;
        a[i] = v + ((u == 0) ? 0.0f : NEGF);
    }

#pragma unroll
    for (int j = 0; j < E_; j++) {
        int idx = lane + 32 * j;
        bool ok = idx < U_;
        sb[1][idx] = ok ? lp[(size_t)1 * U_ + idx] : NEGF;
        sb[0][idx] = ok ? lp[(size_t)2 * U_ + idx] : NEGF;
        pfA[j] = (ok && 3 < alen) ? lp[(size_t)3 * U_ + idx] : NEGF;
        pfB[j] = (ok && 4 < alen) ? lp[(size_t)4 * U_ + idx] : NEGF;
    }
    __syncwarp();

    float c[E_];
    int t = 1;
    for (; t + 1 < alen; t += 2) {
#pragma unroll
        for (int i = 0; i < E_; i++) c[i] = sb[1][u0 + i];
        stepf(a, c, lane);
        __syncwarp();
#pragma unroll
        for (int j = 0; j < E_; j++) {
            int idx = lane + 32 * j;
            sb[1][idx] = pfA[j];
            pfA[j] = (t + 4 < alen && idx < U_) ? lp[(size_t)(t + 4) * U_ + idx] : NEGF;
        }
        __syncwarp();
#pragma unroll
        for (int i = 0; i < E_; i++) c[i] = sb[0][u0 + i];
        stepf(a, c, lane);
        __syncwarp();
#pragma unroll
        for (int j = 0; j < E_; j++) {
            int idx = lane + 32 * j;
            sb[0][idx] = pfB[j];
            pfB[j] = (t + 5 < alen && idx < U_) ? lp[(size_t)(t + 5) * U_ + idx] : NEGF;
        }
        __syncwarp();
    }
    if (t < alen) {
#pragma unroll
        for (int i = 0; i < E_; i++) c[i] = sb[1][u0 + i];
        stepf(a, c, lane);
    }

    int ustar = tlen - 1;
    int own = ustar / E_, slot = ustar % E_;
    float v = 0.0f;
#pragma unroll
    for (int i = 0; i < E_; i++)
        if (i == slot) v = a[i];
    v = __shfl_sync(0xffffffffu, v, own);
    if (lane == 0) g_loss[chain] = -v;
}

// ---------------- 5) final reduction ----------------
__global__ void loss_kernel(float* out)
{
    if (threadIdx.x == 0) {
        float l1 = 0.0f, l2 = 0.0f;
        for (int i = 0; i < 16; i++) { l1 += g_loss[i]; l2 += g_loss[16 + i]; }
        l1 *= (1.0f / 16.0f);
        l2 *= (1.0f / 16.0f);
        out[0] = l1 - 0.5f * l2;
        out[1] = l1;
        out[2] = l2;
    }
}

// ---------------- launch ----------------
extern "C" void kernel_launch(void* const* d_in, const int* in_sizes, int n_in,
                              void* d_out, int out_size)
{
    const float* x    = (const float*)d_in[0];
    const float* W    = (const float*)d_in[1];
    const float* bias = (const float*)d_in[2];
    const int* tgt1   = (const int*)d_in[3];
    const int* tgt2   = (const int*)d_in[4];
    const int* alen   = (const int*)d_in[5];
    const int* tl1    = (const int*)d_in[6];
    const int* tl2    = (const int*)d_in[7];
    float* out = (float*)d_out;

    cvt_x_kernel<<<(M_ * D_ / 8 + 255) / 256, 256>>>(x);   // launch 1
    cvt_w_kernel<<<(D_ * C_ / 8 + 255) / 256, 256>>>(W);   // launch 2
    noop_kernel<<<1, 32>>>();                               // launch 3 (profiling slot-shift)

    dim3 ggrid(C_ / 128, M_ / 128);                         // launch 4 = GEMM
    gemm_bf16_kernel<<<ggrid, 256>>>(bias);

    lse_kernel<<<M_, 256>>>();

    dim3 grid_g((T_ + GT - 1) / GT, 2 * B_);
    gather_kernel<<<grid_g, 128>>>(tgt1, tgt2, alen, tl1, tl2);

    alpha_kernel<<<2 * B_, 32>>>(alen, tl1, tl2);

    loss_kernel<<<1, 32>>>(out);
}

// round 5
// speedup vs baseline: 1.1096x; 1.0556x over previous
#include <cuda_runtime.h>
#include <cuda_bf16.h>
#include <math.h>
#include <stdint.h>

#define B_ 16
#define T_ 2000
#define U_ 400
#define D_ 512
#define C_ 4096
#define M_ (B_ * T_)   // 32000
#define NEGF (-1e30f)

// ---------------- device scratch ----------------
__device__ __align__(16) __nv_bfloat16 g_logits[(size_t)M_ * C_];  // 256 MB
__device__ float g_lp[(size_t)2 * B_ * T_ * U_];                   // 102 MB
__device__ float g_loss[2 * B_];
__device__ __align__(16) __nv_bfloat16 g_xb[(size_t)M_ * D_];
__device__ __align__(16) __nv_bfloat16 g_Wb[(size_t)D_ * C_];

__device__ __forceinline__ float laef(float a, float b) {
    float mx = fmaxf(a, b);
    float d  = fminf(a, b) - mx;
    return mx + __logf(1.0f + __expf(d));
}

// ---------------- 0) fp32 -> bf16 conversion (x and W in one kernel) ----
__device__ __forceinline__ void cvt8(const float* __restrict__ in,
                                     __nv_bfloat16* __restrict__ out, int i) {
    const float4* p = (const float4*)in + (size_t)i * 2;
    float4 v0 = p[0], v1 = p[1];
    __nv_bfloat162 b0 = __floats2bfloat162_rn(v0.x, v0.y);
    __nv_bfloat162 b1 = __floats2bfloat162_rn(v0.z, v0.w);
    __nv_bfloat162 b2 = __floats2bfloat162_rn(v1.x, v1.y);
    __nv_bfloat162 b3 = __floats2bfloat162_rn(v1.z, v1.w);
    uint4 o;
    o.x = *reinterpret_cast<unsigned*>(&b0);
    o.y = *reinterpret_cast<unsigned*>(&b1);
    o.z = *reinterpret_cast<unsigned*>(&b2);
    o.w = *reinterpret_cast<unsigned*>(&b3);
    *((uint4*)out + i) = o;
}

#define NXC ((M_ * D_) / 8)
#define NWC ((D_ * C_) / 8)
__global__ __launch_bounds__(256) void cvt_all_kernel(
    const float* __restrict__ x, const float* __restrict__ W) {
    int i = blockIdx.x * 256 + threadIdx.x;
    if (i < NXC) cvt8(x, g_xb, i);
    else if (i < NXC + NWC) cvt8(W, g_Wb, i - NXC);
}

// ---------------- 1) bf16 tensor-core GEMM, cp.async 3-stage ----------------
#define BK 32
#define STG 3
#define PA 8
#define PB 8

__device__ __forceinline__ void cpa16(uint32_t dst, const void* src) {
    asm volatile("cp.async.cg.shared.global [%0], [%1], 16;\n"
                 :: "r"(dst), "l"(src));
}
__device__ __forceinline__ void cpa_commit() {
    asm volatile("cp.async.commit_group;\n" ::: "memory");
}
template <int N>
__device__ __forceinline__ void cpa_wait() {
    asm volatile("cp.async.wait_group %0;\n" :: "n"(N) : "memory");
}

__global__ __launch_bounds__(256) void gemm_bf16_kernel(const float* __restrict__ bias)
{
    __shared__ __nv_bfloat16 As[STG][128][BK + PA];
    __shared__ __nv_bfloat16 Bs[STG][BK][128 + PB];

    const int tid = threadIdx.x;
    const int wid = tid >> 5, lane = tid & 31;
    const int bm = blockIdx.y, bn = blockIdx.x;
    const int wm = wid & 1, wn = wid >> 1;

    const __nv_bfloat16* gAr = g_xb + (size_t)(bm * 128) * D_;
    const __nv_bfloat16* gBr = g_Wb + bn * 128;

    const uint32_t aBase = (uint32_t)__cvta_generic_to_shared(&As[0][0][0]);
    const uint32_t bBase = (uint32_t)__cvta_generic_to_shared(&Bs[0][0][0]);
    const uint32_t AstgSz = sizeof(As[0]);
    const uint32_t BstgSz = sizeof(Bs[0]);

    auto issue = [&](int s, int k0) {
#pragma unroll
        for (int l = 0; l < 2; l++) {
            int c = tid * 2 + l;
            int ar = c >> 2, ac = (c & 3) * 8;
            cpa16(aBase + s * AstgSz + (ar * (BK + PA) + ac) * 2,
                  gAr + (size_t)ar * D_ + k0 + ac);
        }
#pragma unroll
        for (int l = 0; l < 2; l++) {
            int c = tid * 2 + l;
            int br = c >> 4, bc = (c & 15) * 8;
            cpa16(bBase + s * BstgSz + (br * (128 + PB) + bc) * 2,
                  gBr + (size_t)(k0 + br) * C_ + bc);
        }
    };

    const int aRow = wm * 64 + (lane & 7) + ((lane >> 3) & 1) * 8;
    const int aColHalf = ((lane >> 4) & 1) * 8;
    const int bRowHalf = (lane & 7) + ((lane >> 3) & 1) * 8;
    const int bColBase = wn * 32 + ((lane >> 4) & 1) * 8;

    float acc[4][4][4];
#pragma unroll
    for (int mt = 0; mt < 4; mt++)
#pragma unroll
        for (int nt = 0; nt < 4; nt++)
#pragma unroll
            for (int j = 0; j < 4; j++) acc[mt][nt][j] = 0.0f;

    issue(0, 0);  cpa_commit();
    issue(1, BK); cpa_commit();

    const int NKT = D_ / BK;   // 16
#pragma unroll 1
    for (int kt = 0; kt < NKT; kt++) {
        cpa_wait<1>();
        __syncthreads();

        if (kt + 2 < NKT) issue((kt + 2) % STG, (kt + 2) * BK);
        cpa_commit();

        const int p = kt % STG;
#pragma unroll
        for (int ks = 0; ks < 2; ks++) {
            uint32_t a[4][4], b[2][4];
#pragma unroll
            for (int mt = 0; mt < 4; mt++) {
                uint32_t addr = aBase + p * AstgSz +
                    ((aRow + mt * 16) * (BK + PA) + ks * 16 + aColHalf) * 2;
                asm volatile("ldmatrix.sync.aligned.m8n8.x4.shared.b16 {%0,%1,%2,%3}, [%4];"
                    : "=r"(a[mt][0]), "=r"(a[mt][1]), "=r"(a[mt][2]), "=r"(a[mt][3])
                    : "r"(addr));
            }
#pragma unroll
            for (int pr = 0; pr < 2; pr++) {
                uint32_t addr = bBase + p * BstgSz +
                    ((ks * 16 + bRowHalf) * (128 + PB) + bColBase + pr * 16) * 2;
                asm volatile("ldmatrix.sync.aligned.m8n8.x4.trans.shared.b16 {%0,%1,%2,%3}, [%4];"
                    : "=r"(b[pr][0]), "=r"(b[pr][1]), "=r"(b[pr][2]), "=r"(b[pr][3])
                    : "r"(addr));
            }
#pragma unroll
            for (int mt = 0; mt < 4; mt++)
#pragma unroll
                for (int nt = 0; nt < 4; nt++) {
                    uint32_t b0 = b[nt >> 1][(nt & 1) * 2 + 0];
                    uint32_t b1 = b[nt >> 1][(nt & 1) * 2 + 1];
                    asm volatile(
                        "mma.sync.aligned.m16n8k16.row.col.f32.bf16.bf16.f32 "
                        "{%0,%1,%2,%3}, {%4,%5,%6,%7}, {%8,%9}, {%0,%1,%2,%3};"
                        : "+f"(acc[mt][nt][0]), "+f"(acc[mt][nt][1]),
                          "+f"(acc[mt][nt][2]), "+f"(acc[mt][nt][3])
                        : "r"(a[mt][0]), "r"(a[mt][1]), "r"(a[mt][2]), "r"(a[mt][3]),
                          "r"(b0), "r"(b1));
                }
        }
        __syncthreads();
    }

    const int tig = lane & 3, grp = lane >> 2;
#pragma unroll
    for (int mt = 0; mt < 4; mt++) {
        int row0 = bm * 128 + wm * 64 + mt * 16 + grp;
#pragma unroll
        for (int nt = 0; nt < 4; nt++) {
            int col = bn * 128 + wn * 32 + nt * 8 + 2 * tig;
            float b0v = bias[col], b1v = bias[col + 1];
            __nv_bfloat162 p0 = __floats2bfloat162_rn(acc[mt][nt][0] + b0v,
                                                      acc[mt][nt][1] + b1v);
            __nv_bfloat162 p1 = __floats2bfloat162_rn(acc[mt][nt][2] + b0v,
                                                      acc[mt][nt][3] + b1v);
            *(__nv_bfloat162*)&g_logits[(size_t)row0 * C_ + col] = p0;
            *(__nv_bfloat162*)&g_logits[(size_t)(row0 + 8) * C_ + col] = p1;
        }
    }
}

// ---------------- 2) fused logsumexp + gather ----------------
// one block per (t, b): load bf16 row into smem, block-reduce lse,
// then gather both chains' targets from smem.
__global__ __launch_bounds__(256) void lse_gather_kernel(
    const int* __restrict__ tgt1, const int* __restrict__ tgt2,
    const int* __restrict__ act_lens,
    const int* __restrict__ tl1, const int* __restrict__ tl2)
{
    int t = blockIdx.x, b = blockIdx.y;
    int alen = act_lens[b];
    if (t >= alen) return;

    __shared__ uint16_t srow[C_];    // 8 KB
    __shared__ float red[256];
    int tid = threadIdx.x;
    int row = b * T_ + t;

    const uint4* rp = (const uint4*)(g_logits + (size_t)row * C_);
    uint4 v0 = rp[tid], v1 = rp[tid + 256];
    ((uint4*)srow)[tid] = v0;
    ((uint4*)srow)[tid + 256] = v1;

    uint32_t w[8] = {v0.x, v0.y, v0.z, v0.w, v1.x, v1.y, v1.z, v1.w};
    float f[16];
#pragma unroll
    for (int i = 0; i < 8; i++) {
        float2 p = __bfloat1622float2(*reinterpret_cast<__nv_bfloat162*>(&w[i]));
        f[2 * i] = p.x; f[2 * i + 1] = p.y;
    }

    float mx = -1e30f;
#pragma unroll
    for (int i = 0; i < 16; i++) mx = fmaxf(mx, f[i]);
    red[tid] = mx;
    __syncthreads();
    for (int s = 128; s > 0; s >>= 1) {
        if (tid < s) red[tid] = fmaxf(red[tid], red[tid + s]);
        __syncthreads();
    }
    mx = red[0];
    __syncthreads();

    float sum = 0.0f;
#pragma unroll
    for (int i = 0; i < 16; i++) sum += __expf(f[i] - mx);
    red[tid] = sum;
    __syncthreads();
    for (int s = 128; s > 0; s >>= 1) {
        if (tid < s) red[tid] += red[tid + s];
        __syncthreads();
    }
    float lse = mx + __logf(red[0]);
    // srow writes + reduction barriers already synchronized; smem row is ready

#pragma unroll
    for (int s = 0; s < 2; s++) {
        const int* tgt = (s ? tgt2 : tgt1) + b * U_;
        int tlen = (s ? tl2 : tl1)[b];
        float* lprow = g_lp + ((size_t)(s * B_ + b) * T_ + t) * U_;
#pragma unroll
        for (int u = tid; u < U_; u += 256) {
            float val = NEGF;
            if (u < tlen) {
                uint16_t raw = srow[__ldg(tgt + u)];
                val = __bfloat162float(*reinterpret_cast<__nv_bfloat16*>(&raw)) - lse;
            }
            lprow[u] = val;
        }
    }
}

// ---------------- 3) alpha recursion: ONE WARP per chain ----------------
#define E_ 13   // 13*32 = 416 >= U_
__device__ __forceinline__ void stepf(float* a, const float* c, int lane)
{
    float up = __shfl_up_sync(0xffffffffu, a[E_ - 1], 1);
    if (lane == 0) up = NEGF;
    float prev = up;
#pragma unroll
    for (int i = 0; i < E_; i++) {
        float old = a[i];
        a[i] = laef(old, prev) + c[i];
        prev = old;
    }
}

__global__ __launch_bounds__(32) void alpha_kernel(
    const int* __restrict__ act_lens,
    const int* __restrict__ tl1, const int* __restrict__ tl2)
{
    int chain = blockIdx.x;
    int s = chain >> 4, b = chain & 15;
    int tlen = (s ? tl2 : tl1)[b];
    int alen = act_lens[b];          // >= 1000
    int lane = threadIdx.x;
    const float* lp = g_lp + (size_t)chain * T_ * U_;

    __shared__ float sb[2][416];
    float a[E_], pfA[E_], pfB[E_];
    int u0 = lane * E_;

#pragma unroll
    for (int i = 0; i < E_; i++) {
        int u = u0 + i;
        float v = (u < U_) ? lp[u] : NEGF;
        a[i] = v + ((u == 0) ? 0.0f : NEGF);
    }

#pragma unroll
    for (int j = 0; j < E_; j++) {
        int idx = lane + 32 * j;
        bool ok = idx < U_;
        sb[1][idx] = ok ? lp[(size_t)1 * U_ + idx] : NEGF;
        sb[0][idx] = ok ? lp[(size_t)2 * U_ + idx] : NEGF;
        pfA[j] = (ok && 3 < alen) ? lp[(size_t)3 * U_ + idx] : NEGF;
        pfB[j] = (ok && 4 < alen) ? lp[(size_t)4 * U_ + idx] : NEGF;
    }
    __syncwarp();

    float c[E_];
    int t = 1;
    for (; t + 1 < alen; t += 2) {
#pragma unroll
        for (int i = 0; i < E_; i++) c[i] = sb[1][u0 + i];
        stepf(a, c, lane);
        __syncwarp();
#pragma unroll
        for (int j = 0; j < E_; j++) {
            int idx = lane + 32 * j;
            sb[1][idx] = pfA[j];
            pfA[j] = (t + 4 < alen && idx < U_) ? lp[(size_t)(t + 4) * U_ + idx] : NEGF;
        }
        __syncwarp();
#pragma unroll
        for (int i = 0; i < E_; i++) c[i] = sb[0][u0 + i];
        stepf(a, c, lane);
        __syncwarp();
#pragma unroll
        for (int j = 0; j < E_; j++) {
            int idx = lane + 32 * j;
            sb[0][idx] = pfB[j];
            pfB[j] = (t + 5 < alen && idx < U_) ? lp[(size_t)(t + 5) * U_ + idx] : NEGF;
        }
        __syncwarp();
    }
    if (t < alen) {
#pragma unroll
        for (int i = 0; i < E_; i++) c[i] = sb[1][u0 + i];
        stepf(a, c, lane);
    }

    int ustar = tlen - 1;
    int own = ustar / E_, slot = ustar % E_;
    float v = 0.0f;
#pragma unroll
    for (int i = 0; i < E_; i++)
        if (i == slot) v = a[i];
    v = __shfl_sync(0xffffffffu, v, own);
    if (lane == 0) g_loss[chain] = -v;
}

// ---------------- 4) final reduction ----------------
__global__ void loss_kernel(float* out)
{
    if (threadIdx.x == 0) {
        float l1 = 0.0f, l2 = 0.0f;
        for (int i = 0; i < 16; i++) { l1 += g_loss[i]; l2 += g_loss[16 + i]; }
        l1 *= (1.0f / 16.0f);
        l2 *= (1.0f / 16.0f);
        out[0] = l1 - 0.5f * l2;
        out[1] = l1;
        out[2] = l2;
    }
}

// ---------------- launch ----------------
extern "C" void kernel_launch(void* const* d_in, const int* in_sizes, int n_in,
                              void* d_out, int out_size)
{
    const float* x    = (const float*)d_in[0];
    const float* W    = (const float*)d_in[1];
    const float* bias = (const float*)d_in[2];
    const int* tgt1   = (const int*)d_in[3];
    const int* tgt2   = (const int*)d_in[4];
    const int* alen   = (const int*)d_in[5];
    const int* tl1    = (const int*)d_in[6];
    const int* tl2    = (const int*)d_in[7];
    float* out = (float*)d_out;

    cvt_all_kernel<<<(NXC + NWC + 255) / 256, 256>>>(x, W);   // launch 1

    dim3 ggrid(C_ / 128, M_ / 128);                           // launch 2
    gemm_bf16_kernel<<<ggrid, 256>>>(bias);

    dim3 lgrid(T_, B_);                                       // launch 3
    lse_gather_kernel<<<lgrid, 256>>>(tgt1, tgt2, alen, tl1, tl2);

    alpha_kernel<<<2 * B_, 32>>>(alen, tl1, tl2);             // launch 4 = profiled

    loss_kernel<<<1, 32>>>(out);                              // launch 5
}